// round 7
// baseline (speedup 1.0000x reference)
#include <cuda_runtime.h>

#define N_ORB 256
#define NF    128
#define S     132          // padded row stride (floats); rows 16B-aligned
#define NB    8            // panel width
#define BATCH 4096
#define NTHREADS 256

// Factor an NB-wide panel (cols kb..kb+NB-1, pivot over logical rows >= k)
// entirely inside one warp's registers. Lane holds logical rows 4*lane..4*lane+3.
// L stays raw (unscaled); pivots and reciprocals exported via s_piv / s_inv.
__device__ __forceinline__ void panel_factor(
    float* __restrict__ As, const int* __restrict__ rowoff,
    int* __restrict__ perm, int* __restrict__ s_prow,
    float* __restrict__ s_inv, float* __restrict__ s_piv,
    int kb, int lane)
{
    float a[4][8];
    #pragma unroll
    for (int r = 0; r < 4; r++) {
        const int off = rowoff[4 * lane + r] + kb;
        *(float4*)&a[r][0] = *(const float4*)&As[off];
        *(float4*)&a[r][4] = *(const float4*)&As[off + 4];
    }
    #pragma unroll
    for (int m = 0; m < NB; m++) {
        const int k = kb + m;
        unsigned key = 0u;
        #pragma unroll
        for (int r = 0; r < 4; r++) {
            const int row = 4 * lane + r;
            if (row >= k) {
                unsigned kk = (__float_as_uint(fabsf(a[r][m])) & 0xFFFFFF80u)
                              | (unsigned)row;
                key = max(key, kk);
            }
        }
        key = __reduce_max_sync(0xffffffffu, key);
        const int p  = (int)(key & 127u);
        const int tk = k >> 2, lk = k & 3;
        const int tp = p >> 2, lp = p & 3;

        float rowk[8], rowp[8];
        #pragma unroll
        for (int j = 0; j < 8; j++) {
            float vk = a[0][j];
            if (lk == 1) vk = a[1][j];
            if (lk == 2) vk = a[2][j];
            if (lk == 3) vk = a[3][j];
            rowk[j] = __shfl_sync(0xffffffffu, vk, tk);
            float vp = a[0][j];
            if (lp == 1) vp = a[1][j];
            if (lp == 2) vp = a[2][j];
            if (lp == 3) vp = a[3][j];
            rowp[j] = __shfl_sync(0xffffffffu, vp, tp);
        }
        const float pivot = rowp[m];
        const float inv   = 1.0f / pivot;

        #pragma unroll
        for (int r = 0; r < 4; r++) {
            const bool isk = (lane == tk) && (r == lk);
            const bool isp = (lane == tp) && (r == lp);
            #pragma unroll
            for (int j = 0; j < 8; j++) {
                if (isk)      a[r][j] = rowp[j];
                else if (isp) a[r][j] = rowk[j];
            }
        }
        if (lane == 0) {
            s_inv[m] = inv;
            s_piv[k] = pivot;
            if (p != k) { int t0 = perm[k]; perm[k] = perm[p]; perm[p] = t0; }
        }
        __syncwarp();

        float u[8];
        #pragma unroll
        for (int j = 0; j < 8; j++) u[j] = inv * rowp[j];
        #pragma unroll
        for (int r = 0; r < 4; r++) {
            const int row = 4 * lane + r;
            if (row > k) {
                const float mult = a[r][m];
                #pragma unroll
                for (int j = 0; j < 8; j++)
                    if (j > m) a[r][j] -= mult * u[j];
            }
        }
    }
    #pragma unroll
    for (int r = 0; r < 4; r++) {
        const int off = perm[4 * lane + r] * S + kb;
        *(float4*)&As[off]     = *(float4*)&a[r][0];
        *(float4*)&As[off + 4] = *(float4*)&a[r][4];
    }
    if (lane < NB) s_prow[lane] = perm[kb + lane] * S;
    __syncwarp();
}

__global__ __launch_bounds__(NTHREADS, 3)
void slater_logdet_kernel(const int* __restrict__ n_occ,
                          const float* __restrict__ M,
                          float* __restrict__ out)
{
    extern __shared__ float As[];            // NF * S floats
    __shared__ int   Rsh[NF];
    __shared__ int   warpCnt[8];
    __shared__ int   perm[NF];               // logical row -> physical row
    __shared__ int   rowoff[NF];             // perm snapshot * S
    __shared__ int   s_prow[2][NB];          // double-buffered panel row offsets
    __shared__ float s_inv[2][NB];           // double-buffered pivot reciprocals
    __shared__ float s_piv[NF];
    __shared__ float s_red[8];

    const int b    = blockIdx.x;
    const int tid  = threadIdx.x;
    const int lane = tid & 31;
    const int wid  = tid >> 5;

    // ---- Phase 1: occupied orbital indices, ascending (ballot + scan) ----
    int occ = (n_occ[b * N_ORB + tid] != 0);
    unsigned bm = __ballot_sync(0xffffffffu, occ);
    int rank = __popc(bm & ((1u << lane) - 1u));
    if (lane == 0) warpCnt[wid] = __popc(bm);
    if (tid < NF) { perm[tid] = tid; rowoff[tid] = tid * S; }
    __syncthreads();
    int base = 0;
    #pragma unroll
    for (int w = 0; w < 8; w++) if (w < wid) base += warpCnt[w];
    if (occ) Rsh[base + rank] = tid;
    __syncthreads();

    // ---- Phase 2: gather A[f][:] = M[R[f]][:]  (float4) ----
    const float4* M4 = (const float4*)M;
    #pragma unroll
    for (int t = 0; t < 16; t++) {
        int idx = tid + t * NTHREADS;
        int f = idx >> 5;
        int q = idx & 31;
        float4 v = M4[Rsh[f] * 32 + q];
        *(float4*)&As[f * S + 4 * q] = v;
    }
    __syncthreads();

    // ---- Phase 3: blocked LU, lookahead, no trsm pass (V in registers) ----
    if (wid == 0)
        panel_factor(As, rowoff, perm, s_prow[0], s_inv[0], s_piv, 0, lane);
    __syncthreads();

    for (int kb = 0; kb < NF - NB; kb += NB) {
        const int c0    = kb + NB;
        const int buf   = (kb >> 3) & 1;
        const int nrows = NF - c0;

        // ---- step A: refresh rowoff snapshot + narrow update of next panel
        //      columns [c0, c0+8). Each thread owns column jj = c0 + (tid&7),
        //      computes V[:,jj] in registers (L11 recurrence, raw A12 reads),
        //      then updates its strided rows. Nothing written to the U12 block.
        if (tid < NF) rowoff[tid] = perm[tid] * S;
        {
            const int jj = c0 + (tid & 7);
            float v[NB];
            #pragma unroll
            for (int m = 0; m < NB; m++) {
                const int pr = s_prow[buf][m];
                float acc = As[pr + jj];
                #pragma unroll
                for (int t2 = 0; t2 < m; t2++)
                    acc -= As[pr + kb + t2] * v[t2];   // broadcast L11 reads
                v[m] = acc * s_inv[buf][m];
            }
            for (int r = c0 + (tid >> 3); r < NF; r += 32) {
                const int o = perm[r] * S;
                float acc = As[o + jj];
                #pragma unroll
                for (int m = 0; m < NB; m++)
                    acc -= As[o + kb + m] * v[m];
                As[o + jj] = acc;
            }
        }
        __syncthreads();

        // ---- step B (concurrent): warp 0 factors the NEXT panel; warps 1..7
        //      bulk-GEMM the remaining trailing columns with panel kb,
        //      hoisting V per column tile via the same in-register recurrence.
        if (wid == 0) {
            panel_factor(As, rowoff, perm, s_prow[buf ^ 1], s_inv[buf ^ 1],
                         s_piv, c0, lane);
        } else {
            const int ncols2 = nrows - NB;        // cols [c0+8, 128)
            if (ncols2 > 0) {
                const int nct = ncols2 >> 2;
                const int nrt = nrows  >> 2;
                if (lane < nct) {
                    const int j0 = c0 + NB + 4 * lane;

                    // V block for this column tile (registers only)
                    float uu[NB][4];
                    #pragma unroll
                    for (int m = 0; m < NB; m++) {
                        const int pr = s_prow[buf][m];
                        float4 raw = *(const float4*)&As[pr + j0];
                        float a0 = raw.x, a1 = raw.y, a2 = raw.z, a3 = raw.w;
                        #pragma unroll
                        for (int t2 = 0; t2 < m; t2++) {
                            const float l11 = As[pr + kb + t2];
                            a0 -= l11 * uu[t2][0];
                            a1 -= l11 * uu[t2][1];
                            a2 -= l11 * uu[t2][2];
                            a3 -= l11 * uu[t2][3];
                        }
                        const float iv = s_inv[buf][m];
                        uu[m][0] = a0 * iv; uu[m][1] = a1 * iv;
                        uu[m][2] = a2 * iv; uu[m][3] = a3 * iv;
                    }

                    for (int tr = wid - 1; tr < nrt; tr += 7) {
                        const int r0 = c0 + 4 * tr;
                        const int o0 = rowoff[r0],     o1 = rowoff[r0 + 1];
                        const int o2 = rowoff[r0 + 2], o3 = rowoff[r0 + 3];

                        float a0[4], a1[4], a2[4], a3[4];
                        *(float4*)a0 = *(const float4*)&As[o0 + j0];
                        *(float4*)a1 = *(const float4*)&As[o1 + j0];
                        *(float4*)a2 = *(const float4*)&As[o2 + j0];
                        *(float4*)a3 = *(const float4*)&As[o3 + j0];

                        #pragma unroll
                        for (int h = 0; h < 2; h++) {
                            float l0[4], l1[4], l2[4], l3[4];
                            *(float4*)l0 = *(const float4*)&As[o0 + kb + 4 * h];
                            *(float4*)l1 = *(const float4*)&As[o1 + kb + 4 * h];
                            *(float4*)l2 = *(const float4*)&As[o2 + kb + 4 * h];
                            *(float4*)l3 = *(const float4*)&As[o3 + kb + 4 * h];
                            #pragma unroll
                            for (int mm = 0; mm < 4; mm++) {
                                const int m = 4 * h + mm;
                                #pragma unroll
                                for (int c = 0; c < 4; c++) {
                                    a0[c] -= l0[mm] * uu[m][c];
                                    a1[c] -= l1[mm] * uu[m][c];
                                    a2[c] -= l2[mm] * uu[m][c];
                                    a3[c] -= l3[mm] * uu[m][c];
                                }
                            }
                        }
                        *(float4*)&As[o0 + j0] = *(float4*)a0;
                        *(float4*)&As[o1 + j0] = *(float4*)a1;
                        *(float4*)&As[o2 + j0] = *(float4*)a2;
                        *(float4*)&As[o3 + j0] = *(float4*)a3;
                    }
                }
            }
        }
        __syncthreads();
    }

    // ---- Phase 4: logabs = sum log|pivot| ----
    float lsum = 0.0f;
    if (tid < NF) lsum = logf(fabsf(s_piv[tid]));
    #pragma unroll
    for (int o = 16; o; o >>= 1) lsum += __shfl_down_sync(0xffffffffu, lsum, o);
    if (lane == 0) s_red[wid] = lsum;
    __syncthreads();
    if (tid == 0) {
        float tot = 0.0f;
        #pragma unroll
        for (int w = 0; w < 8; w++) tot += s_red[w];
        out[b] = tot;
    }
}

extern "C" void kernel_launch(void* const* d_in, const int* in_sizes, int n_in,
                              void* d_out, int out_size)
{
    (void)in_sizes; (void)n_in; (void)out_size;
    const int*   n_occ = (const int*)d_in[0];
    const float* M     = (const float*)d_in[1];
    float*       out   = (float*)d_out;

    const int smem = NF * S * (int)sizeof(float);   // 67584 bytes dynamic
    cudaFuncSetAttribute(slater_logdet_kernel,
                         cudaFuncAttributeMaxDynamicSharedMemorySize, smem);
    slater_logdet_kernel<<<BATCH, NTHREADS, smem>>>(n_occ, M, out);
}

// round 8
// speedup vs baseline: 1.6876x; 1.6876x over previous
#include <cuda_runtime.h>

#define N_ORB 256
#define NF    128
#define S     132          // padded row stride (floats); rows 16B-aligned
#define NB    8            // panel width
#define BATCH 4096
#define NTHREADS 256

// Virtual-pivot panel factorization: cols [kb, kb+NB), candidate rows >= kb.
// Lane holds logical rows 4*lane+r. Rows NEVER move; pivoting is logical:
// chosen rows are marked done and perm[] is rebuilt at the end.
// L stays raw; pivots / reciprocals exported via s_piv / s_inv; s_prow gets
// the physical row offsets of the NB pivot rows (in choice order).
__device__ __forceinline__ void panel_factor(
    float* __restrict__ As, const int* __restrict__ rowoff,
    int* __restrict__ perm, int* __restrict__ s_prow,
    float* __restrict__ s_inv, float* __restrict__ s_piv,
    int kb, int lane)
{
    float a[4][8];
    int   rof[4];
    bool  act[4];
    int   chm[4] = {-1, -1, -1, -1};

    #pragma unroll
    for (int r = 0; r < 4; r++) {
        const int row = 4 * lane + r;
        act[r] = (row >= kb);
        rof[r] = rowoff[row];
        if (act[r]) {
            *(float4*)&a[r][0] = *(const float4*)&As[rof[r] + kb];
            *(float4*)&a[r][4] = *(const float4*)&As[rof[r] + kb + 4];
        }
    }

    #pragma unroll
    for (int m = 0; m < NB; m++) {
        // argmax |a[.][m]| over active rows (packed key: abs bits | row index)
        unsigned key = 0u;
        #pragma unroll
        for (int r = 0; r < 4; r++)
            if (act[r]) {
                unsigned kk = (__float_as_uint(fabsf(a[r][m])) & 0xFFFFFF80u)
                              | (unsigned)(4 * lane + r);
                key = max(key, kk);
            }
        key = __reduce_max_sync(0xffffffffu, key);
        const int p  = (int)(key & 127u);
        const int tp = p >> 2, lp = p & 3;

        // broadcast pivot row (needed for the update anyway)
        float rowp[8];
        #pragma unroll
        for (int j = 0; j < 8; j++) {
            float vp = a[0][j];
            if (lp == 1) vp = a[1][j];
            if (lp == 2) vp = a[2][j];
            if (lp == 3) vp = a[3][j];
            rowp[j] = __shfl_sync(0xffffffffu, vp, tp);
        }
        const float pivot = rowp[m];
        const float inv   = 1.0f / pivot;
        if (lane == 0) { s_inv[m] = inv; s_piv[kb + m] = pivot; }
        #pragma unroll
        for (int r = 0; r < 4; r++)
            if (lane == tp && r == lp) { act[r] = false; chm[r] = m; }

        float u[8];
        #pragma unroll
        for (int j = 0; j < 8; j++) u[j] = inv * rowp[j];
        #pragma unroll
        for (int r = 0; r < 4; r++)
            if (act[r]) {
                const float mult = a[r][m];
                #pragma unroll
                for (int j = m + 1; j < 8; j++) a[r][j] -= mult * u[j];
            }
    }

    // write back rows >= kb (in place; physical rows stationary)
    #pragma unroll
    for (int r = 0; r < 4; r++) {
        if (4 * lane + r >= kb) {
            *(float4*)&As[rof[r] + kb]     = *(float4*)&a[r][0];
            *(float4*)&As[rof[r] + kb + 4] = *(float4*)&a[r][4];
        }
    }

    // rebuild perm: chosen rows -> kb+m (choice order); unchosen rows >= kb
    // keep relative order at kb+NB... ; rows < kb untouched.
    int pv[4];
    #pragma unroll
    for (int r = 0; r < 4; r++) pv[r] = perm[4 * lane + r];
    __syncwarp();

    unsigned unch[4];
    #pragma unroll
    for (int r = 0; r < 4; r++)
        unch[r] = __ballot_sync(0xffffffffu, (4 * lane + r >= kb) && act[r]);

    #pragma unroll
    for (int r = 0; r < 4; r++) {
        const int row = 4 * lane + r;
        if (row >= kb) {
            if (!act[r]) {                       // chosen pivot row
                perm[kb + chm[r]]  = pv[r];
                s_prow[chm[r]]     = rof[r];
            } else {                             // unchosen: rank among unchosen
                int rank = 0;
                #pragma unroll
                for (int r2 = 0; r2 < 4; r2++)
                    rank += __popc(unch[r2] &
                                   ((r2 < r) ? ((2u << lane) - 1u)
                                             : ((1u << lane) - 1u)));
                perm[kb + NB + rank] = pv[r];
            }
        }
    }
    __syncwarp();
}

__global__ __launch_bounds__(NTHREADS, 3)
void slater_logdet_kernel(const int* __restrict__ n_occ,
                          const float* __restrict__ M,
                          float* __restrict__ out)
{
    extern __shared__ float As[];            // NF * S floats
    __shared__ int   Rsh[NF];
    __shared__ int   warpCnt[8];
    __shared__ int   perm[NF];               // logical row -> physical row
    __shared__ int   rowoff[NF];             // perm snapshot * S
    __shared__ int   s_prow[2][NB];          // double-buffered pivot row offsets
    __shared__ float s_inv[2][NB];           // double-buffered pivot reciprocals
    __shared__ float s_piv[NF];
    __shared__ float s_red[8];

    const int b    = blockIdx.x;
    const int tid  = threadIdx.x;
    const int lane = tid & 31;
    const int wid  = tid >> 5;

    // ---- Phase 1: occupied orbital indices, ascending (ballot + scan) ----
    int occ = (n_occ[b * N_ORB + tid] != 0);
    unsigned bm = __ballot_sync(0xffffffffu, occ);
    int rank = __popc(bm & ((1u << lane) - 1u));
    if (lane == 0) warpCnt[wid] = __popc(bm);
    if (tid < NF) { perm[tid] = tid; rowoff[tid] = tid * S; }
    __syncthreads();
    int base = 0;
    #pragma unroll
    for (int w = 0; w < 8; w++) if (w < wid) base += warpCnt[w];
    if (occ) Rsh[base + rank] = tid;
    __syncthreads();

    // ---- Phase 2: gather A[f][:] = M[R[f]][:]  (float4) ----
    const float4* M4 = (const float4*)M;
    #pragma unroll
    for (int t = 0; t < 16; t++) {
        int idx = tid + t * NTHREADS;
        int f = idx >> 5;
        int q = idx & 31;
        float4 v = M4[Rsh[f] * 32 + q];
        *(float4*)&As[f * S + 4 * q] = v;
    }
    __syncthreads();

    // ---- Phase 3: blocked LU with lookahead (R6 structure, faster panel) ----
    if (wid == 0)
        panel_factor(As, rowoff, perm, s_prow[0], s_inv[0], s_piv, 0, lane);
    __syncthreads();

    for (int kb = 0; kb < NF - NB; kb += NB) {
        const int c0    = kb + NB;
        const int buf   = (kb >> 3) & 1;
        const int nrows = NF - c0;

        // step 1: refresh rowoff (perm after panel kb) + trsm all trailing cols
        // trsm: V = diag(inv) * L11^{-1} * A12, in place; raw L11, broadcasts.
        if (tid < NF) rowoff[tid] = perm[tid] * S;
        if (tid < nrows) {
            const int j = c0 + tid;
            float rhs[NB];
            #pragma unroll
            for (int m = 0; m < NB; m++) rhs[m] = As[s_prow[buf][m] + j];
            float v[NB];
            #pragma unroll
            for (int m = 0; m < NB; m++) {
                float acc = rhs[m];
                #pragma unroll
                for (int t2 = 0; t2 < m; t2++)
                    acc -= As[s_prow[buf][m] + kb + t2] * v[t2];
                v[m] = acc * s_inv[buf][m];
            }
            #pragma unroll
            for (int m = 0; m < NB; m++)
                As[s_prow[buf][m] + j] = v[m];
        }
        __syncthreads();

        // step 2: narrow GEMM — update only next panel's columns [c0, c0+8)
        if (tid < 2 * nrows) {
            const int r  = c0 + (tid >> 1);
            const int j0 = c0 + 4 * (tid & 1);
            const int o  = rowoff[r];
            float l[8];
            *(float4*)&l[0] = *(const float4*)&As[o + kb];
            *(float4*)&l[4] = *(const float4*)&As[o + kb + 4];
            float acc[4];
            *(float4*)acc = *(const float4*)&As[o + j0];
            #pragma unroll
            for (int m = 0; m < NB; m++) {
                float u[4];
                *(float4*)u = *(const float4*)&As[s_prow[buf][m] + j0];
                #pragma unroll
                for (int c = 0; c < 4; c++) acc[c] -= l[m] * u[c];
            }
            *(float4*)&As[o + j0] = *(float4*)acc;
        }
        __syncthreads();

        // step 3 (concurrent): warp 0 factors NEXT panel; warps 1..7 bulk GEMM
        if (wid == 0) {
            panel_factor(As, rowoff, perm, s_prow[buf ^ 1], s_inv[buf ^ 1],
                         s_piv, c0, lane);
        } else {
            const int ncols2 = nrows - NB;        // cols [c0+8, 128)
            if (ncols2 > 0) {
                const int nct = ncols2 >> 2;
                const int nrt = nrows  >> 2;
                if (lane < nct) {
                    const int j0 = c0 + NB + 4 * lane;
                    float uu[8][4];
                    #pragma unroll
                    for (int m = 0; m < NB; m++)
                        *(float4*)&uu[m][0] =
                            *(const float4*)&As[s_prow[buf][m] + j0];

                    for (int tr = wid - 1; tr < nrt; tr += 7) {
                        const int r0 = c0 + 4 * tr;
                        const int o0 = rowoff[r0],     o1 = rowoff[r0 + 1];
                        const int o2 = rowoff[r0 + 2], o3 = rowoff[r0 + 3];

                        float a0[4], a1[4], a2[4], a3[4];
                        *(float4*)a0 = *(const float4*)&As[o0 + j0];
                        *(float4*)a1 = *(const float4*)&As[o1 + j0];
                        *(float4*)a2 = *(const float4*)&As[o2 + j0];
                        *(float4*)a3 = *(const float4*)&As[o3 + j0];

                        #pragma unroll
                        for (int h = 0; h < 2; h++) {
                            float l0[4], l1[4], l2[4], l3[4];
                            *(float4*)l0 = *(const float4*)&As[o0 + kb + 4 * h];
                            *(float4*)l1 = *(const float4*)&As[o1 + kb + 4 * h];
                            *(float4*)l2 = *(const float4*)&As[o2 + kb + 4 * h];
                            *(float4*)l3 = *(const float4*)&As[o3 + kb + 4 * h];
                            #pragma unroll
                            for (int mm = 0; mm < 4; mm++) {
                                const int m = 4 * h + mm;
                                #pragma unroll
                                for (int c = 0; c < 4; c++) {
                                    a0[c] -= l0[mm] * uu[m][c];
                                    a1[c] -= l1[mm] * uu[m][c];
                                    a2[c] -= l2[mm] * uu[m][c];
                                    a3[c] -= l3[mm] * uu[m][c];
                                }
                            }
                        }
                        *(float4*)&As[o0 + j0] = *(float4*)a0;
                        *(float4*)&As[o1 + j0] = *(float4*)a1;
                        *(float4*)&As[o2 + j0] = *(float4*)a2;
                        *(float4*)&As[o3 + j0] = *(float4*)a3;
                    }
                }
            }
        }
        __syncthreads();
    }

    // ---- Phase 4: logabs = sum log|pivot| ----
    float lsum = 0.0f;
    if (tid < NF) lsum = logf(fabsf(s_piv[tid]));
    #pragma unroll
    for (int o = 16; o; o >>= 1) lsum += __shfl_down_sync(0xffffffffu, lsum, o);
    if (lane == 0) s_red[wid] = lsum;
    __syncthreads();
    if (tid == 0) {
        float tot = 0.0f;
        #pragma unroll
        for (int w = 0; w < 8; w++) tot += s_red[w];
        out[b] = tot;
    }
}

extern "C" void kernel_launch(void* const* d_in, const int* in_sizes, int n_in,
                              void* d_out, int out_size)
{
    (void)in_sizes; (void)n_in; (void)out_size;
    const int*   n_occ = (const int*)d_in[0];
    const float* M     = (const float*)d_in[1];
    float*       out   = (float*)d_out;

    const int smem = NF * S * (int)sizeof(float);   // 67584 bytes dynamic
    cudaFuncSetAttribute(slater_logdet_kernel,
                         cudaFuncAttributeMaxDynamicSharedMemorySize, smem);
    slater_logdet_kernel<<<BATCH, NTHREADS, smem>>>(n_occ, M, out);
}